// round 11
// baseline (speedup 1.0000x reference)
#include <cuda_runtime.h>
#include <cuda_bf16.h>
#include <math.h>

#define Bq 4
#define Lq 4096
#define Hq 256
#define NHq 8
#define Tq 64
#define Dq 32
#define WINq 16
#define NEG_SLOPE 5.0f
#define MASK_FILL -1e12f

// ---------------- scratch (device globals; no allocation allowed) ----------------
__device__ float g_U[Bq * Lq * Hq];
__device__ float g_uq[Bq * NHq * Lq];
__device__ float g_ds[Bq * NHq * Lq];
__device__ float g_dt[Bq * NHq * Tq];
__device__ unsigned g_WtHi[3 * 256 * 128];
__device__ unsigned g_WtLo[3 * 256 * 128];
// packed bf16x2 hi/lo operand copies (x = hi, y = lo)
__device__ uint2 g_chP2[Bq * NHq * Lq * 16];      // row-major ch   [b][n][l][kp]
__device__ uint2 g_chT2[Bq * NHq * 32 * 2048];    // transposed ch  [b][n][d][lp]
__device__ uint2 g_tyP2[Bq * NHq * 64 * 16];      // row-major types
__device__ uint2 g_tyT2[Bq * NHq * 32 * 32];      // transposed types
__device__ uint2 g_xP2[NHq * 32 * 16];            // crossT [n][h][kp]

__device__ __forceinline__ float leaky(float x) { return x >= 0.f ? x : NEG_SLOPE * x; }

__device__ __forceinline__ unsigned pack_bf16x2(float lo_elem, float hi_elem) {
    unsigned r;
    asm("cvt.rn.bf16x2.f32 %0, %1, %2;" : "=r"(r) : "f"(hi_elem), "f"(lo_elem));
    return r;
}
__device__ __forceinline__ float bf_lo(unsigned p) { return __uint_as_float(p << 16); }
__device__ __forceinline__ float bf_hi(unsigned p) { return __uint_as_float(p & 0xFFFF0000u); }

__device__ __forceinline__ void mma16bf(float c[4], const unsigned a[4], const unsigned b[2]) {
    asm volatile(
        "mma.sync.aligned.m16n8k16.row.col.f32.bf16.bf16.f32 "
        "{%0,%1,%2,%3}, {%4,%5,%6,%7}, {%8,%9}, {%0,%1,%2,%3};"
        : "+f"(c[0]), "+f"(c[1]), "+f"(c[2]), "+f"(c[3])
        : "r"(a[0]), "r"(a[1]), "r"(a[2]), "r"(a[3]), "r"(b[0]), "r"(b[1]));
}
__device__ __forceinline__ void mma3(float c[4],
                                     const unsigned ahi[4], const unsigned alo[4],
                                     const unsigned bhi[2], const unsigned blo[2]) {
    mma16bf(c, ahi, bhi);
    mma16bf(c, ahi, blo);
    mma16bf(c, alo, bhi);
}

__device__ __forceinline__ void gatherA16(const unsigned* U, int stride,
                                          int R0, int KP0, int lane, unsigned a[4]) {
    int p = (R0 + (lane >> 2)) * stride + KP0 + (lane & 3);
    a[0] = U[p];
    a[1] = U[p + 8 * stride];
    a[2] = U[p + 4];
    a[3] = U[p + 8 * stride + 4];
}
__device__ __forceinline__ void gatherB16(const unsigned* U, int stride,
                                          int N0, int KP0, int lane, unsigned bb[2]) {
    int p = (N0 + (lane >> 2)) * stride + KP0 + (lane & 3);
    bb[0] = U[p];
    bb[1] = U[p + 4];
}

__device__ __forceinline__ void store_split(unsigned* baseHi, unsigned* baseLo,
                                            int halfIdx, float v) {
    __nv_bfloat16 h = __float2bfloat16(v);
    float r = v - __bfloat162float(h);
    ((__nv_bfloat16*)baseHi)[halfIdx] = h;
    ((__nv_bfloat16*)baseLo)[halfIdx] = __float2bfloat16(r);
}

__device__ __forceinline__ int mask_mode(const void* m) {
    unsigned u = *(const unsigned*)m;
    if (u == 0x01010101u) return 0;
    if (u == 0x3F800000u) return 2;
    return 1;
}
__device__ __forceinline__ bool mask_at(const void* m, int mode, long idx) {
    if (mode == 0) return ((const unsigned char*)m)[idx] != 0;
    if (mode == 1) return ((const int*)m)[idx] != 0;
    return ((const float*)m)[idx] != 0.f;
}

// ---------------- prep: transpose + bf16-split the three 256x256 weights -------
__global__ __launch_bounds__(256) void prep_weights(
    const float* __restrict__ W0, const float* __restrict__ W1,
    const float* __restrict__ W2)
{
    __shared__ float s[32][33];
    const int w = blockIdx.z;
    const float* W = (w == 0) ? W0 : (w == 1) ? W1 : W2;
    const int k0 = blockIdx.x * 32, n0 = blockIdx.y * 32;
    const int tid = threadIdx.x;
#pragma unroll
    for (int it = 0; it < 4; it++) {
        int idx = it * 256 + tid;
        int kr = idx >> 5, nc = idx & 31;
        s[kr][nc] = W[(size_t)(k0 + kr) * 256 + n0 + nc];
    }
    __syncthreads();
#pragma unroll
    for (int it = 0; it < 2; it++) {
        int idx = it * 256 + tid;
        int nn = idx >> 4, kp = idx & 15;
        float e0 = s[2 * kp][nn], e1 = s[2 * kp + 1][nn];
        unsigned hi = pack_bf16x2(e0, e1);
        unsigned lo = pack_bf16x2(e0 - bf_lo(hi), e1 - bf_hi(hi));
        size_t o = (size_t)(w * 256 + n0 + nn) * 128 + (k0 >> 1) + kp;
        g_WtHi[o] = hi;
        g_WtLo[o] = lo;
    }
}

// ---------------- prep: pack crossT per head ------------------------------------
__global__ __launch_bounds__(256) void prep_cross(const float* __restrict__ cross)
{
    const int tid = threadIdx.x;
#pragma unroll
    for (int it = 0; it < 16; it++) {
        int idx = it * 256 + tid;              // n*512 + h*16 + kp
        int n = idx >> 9;
        int h = (idx >> 4) & 31;
        int kp = idx & 15;
        float e0 = cross[(size_t)(n * 32 + 2 * kp) * 32 + h];
        float e1 = cross[(size_t)(n * 32 + 2 * kp + 1) * 32 + h];
        unsigned hi = pack_bf16x2(e0, e1);
        unsigned lo = pack_bf16x2(e0 - bf_lo(hi), e1 - bf_hi(hi));
        g_xP2[idx] = make_uint2(hi, lo);
    }
}

// ---------------- bf16x3 GEMM + fused epilogues ---------------------------------
// mode: 0 = plain+tanh -> C; 1 = context (pack ch + uq/ds); 2 = types (pack + dt)
__global__ __launch_bounds__(256) void gemm_bf16x3(
    const float* __restrict__ A, int wsel,
    const float* __restrict__ bias, float* __restrict__ C,
    int mode,
    const float* __restrict__ upon, const float* __restrict__ down)
{
    __shared__ unsigned sAhi[128 * 20];
    __shared__ unsigned sAlo[128 * 20];
    __shared__ unsigned sBhi[64 * 20];
    __shared__ unsigned sBlo[64 * 20];

    const int tid = threadIdx.x;
    const int wid = tid >> 5, lane = tid & 31;
    const int wm = wid >> 1, wn = wid & 1;
    const int bm = blockIdx.y * 128;
    const int bn = blockIdx.x * 64;
    const unsigned* WHi = g_WtHi + (size_t)wsel * 256 * 128;
    const unsigned* WLo = g_WtLo + (size_t)wsel * 256 * 128;

    float acc[2][4][4];
#pragma unroll
    for (int mt = 0; mt < 2; mt++)
#pragma unroll
        for (int nt = 0; nt < 4; nt++)
#pragma unroll
            for (int r = 0; r < 4; r++) acc[mt][nt][r] = 0.f;

    for (int chunk = 0; chunk < 8; chunk++) {
        const int kc0 = chunk * 32;
#pragma unroll
        for (int i = 0; i < 4; i++) {
            int fidx = i * 256 + tid;
            int row = fidx >> 3, col4 = fidx & 7;
            float4 v = *(const float4*)(A + (size_t)(bm + row) * 256 + kc0 + col4 * 4);
            unsigned h0 = pack_bf16x2(v.x, v.y);
            unsigned h1 = pack_bf16x2(v.z, v.w);
            unsigned l0 = pack_bf16x2(v.x - bf_lo(h0), v.y - bf_hi(h0));
            unsigned l1 = pack_bf16x2(v.z - bf_lo(h1), v.w - bf_hi(h1));
            int o = row * 20 + col4 * 2;
            *(uint2*)&sAhi[o] = make_uint2(h0, h1);
            *(uint2*)&sAlo[o] = make_uint2(l0, l1);
        }
#pragma unroll
        for (int i = 0; i < 2; i++) {
            int fidx = i * 256 + tid;
            int row = fidx >> 3, j = fidx & 7;
            size_t src = (size_t)(bn + row) * 128 + (kc0 >> 1) + j * 2;
            int o = row * 20 + j * 2;
            *(uint2*)&sBhi[o] = *(const uint2*)&WHi[src];
            *(uint2*)&sBlo[o] = *(const uint2*)&WLo[src];
        }
        __syncthreads();
#pragma unroll
        for (int k16 = 0; k16 < 2; k16++) {
            unsigned ahi[2][4], alo[2][4];
#pragma unroll
            for (int mt = 0; mt < 2; mt++) {
                gatherA16(sAhi, 20, wm * 32 + mt * 16, k16 * 8, lane, ahi[mt]);
                gatherA16(sAlo, 20, wm * 32 + mt * 16, k16 * 8, lane, alo[mt]);
            }
#pragma unroll
            for (int nt = 0; nt < 4; nt++) {
                unsigned bhi[2], blo[2];
                gatherB16(sBhi, 20, wn * 32 + nt * 8, k16 * 8, lane, bhi);
                gatherB16(sBlo, 20, wn * 32 + nt * 8, k16 * 8, lane, blo);
#pragma unroll
                for (int mt = 0; mt < 2; mt++) {
                    mma16bf(acc[mt][nt], ahi[mt], bhi);
                    mma16bf(acc[mt][nt], ahi[mt], blo);
                    mma16bf(acc[mt][nt], alo[mt], bhi);
                }
            }
        }
        __syncthreads();
    }

    const int row0 = bm + wm * 32 + (lane >> 2);
    const int col0 = bn + wn * 32 + (lane & 3) * 2;

    // add bias
#pragma unroll
    for (int mt = 0; mt < 2; mt++)
#pragma unroll
        for (int nt = 0; nt < 4; nt++) {
            int c = col0 + nt * 8;
            float b0 = bias[c], b1 = bias[c + 1];
            acc[mt][nt][0] += b0; acc[mt][nt][1] += b1;
            acc[mt][nt][2] += b0; acc[mt][nt][3] += b1;
        }

    if (mode == 0) {
#pragma unroll
        for (int mt = 0; mt < 2; mt++)
#pragma unroll
            for (int nt = 0; nt < 4; nt++) {
                int r = row0 + mt * 16;
                int c = col0 + nt * 8;
                float2 o0 = make_float2(tanhf(acc[mt][nt][0]), tanhf(acc[mt][nt][1]));
                float2 o1 = make_float2(tanhf(acc[mt][nt][2]), tanhf(acc[mt][nt][3]));
                *(float2*)(C + (size_t)r * 256 + c)       = o0;
                *(float2*)(C + (size_t)(r + 8) * 256 + c) = o1;
            }
        return;
    }

    // ---- fused row-dots ----
    const int n_h = (bn >> 5) + wn;
    float pa[4] = {0.f, 0.f, 0.f, 0.f};
    float pd[4] = {0.f, 0.f, 0.f, 0.f};
#pragma unroll
    for (int mt = 0; mt < 2; mt++)
#pragma unroll
        for (int nt = 0; nt < 4; nt++) {
            int c = col0 + nt * 8;
            float u0 = upon[c], u1 = upon[c + 1];
            float d0 = down[c], d1 = down[c + 1];
            pa[mt * 2 + 0] += acc[mt][nt][0] * u0 + acc[mt][nt][1] * u1;
            pa[mt * 2 + 1] += acc[mt][nt][2] * u0 + acc[mt][nt][3] * u1;
            pd[mt * 2 + 0] += acc[mt][nt][0] * d0 + acc[mt][nt][1] * d1;
            pd[mt * 2 + 1] += acc[mt][nt][2] * d0 + acc[mt][nt][3] * d1;
        }
#pragma unroll
    for (int j = 0; j < 4; j++) {
        pa[j] += __shfl_xor_sync(0xFFFFFFFFu, pa[j], 1);
        pa[j] += __shfl_xor_sync(0xFFFFFFFFu, pa[j], 2);
        pd[j] += __shfl_xor_sync(0xFFFFFFFFu, pd[j], 1);
        pd[j] += __shfl_xor_sync(0xFFFFFFFFu, pd[j], 2);
    }
    if ((lane & 3) == 0) {
#pragma unroll
        for (int j = 0; j < 4; j++) {
            int row = row0 + (j >> 1) * 16 + (j & 1) * 8;
            if (mode == 1) {
                int b = row >> 12, l = row & 4095;
                g_uq[((size_t)(b * NHq + n_h)) * Lq + l] = pa[j];
                g_ds[((size_t)(b * NHq + n_h)) * Lq + l] = pd[j];
            } else {
                int b = row >> 6, t = row & 63;
                g_dt[(b * NHq + n_h) * Tq + t] = pd[j];
            }
        }
    }

    // ---- packed bf16 hi/lo copies (row-major + transposed) ----
    const int q = lane >> 2;
    const bool evq = (q & 1) == 0;
#pragma unroll
    for (int mt = 0; mt < 2; mt++) {
        int r = row0 + mt * 16;
#pragma unroll
        for (int nt = 0; nt < 4; nt++) {
            float v00 = acc[mt][nt][0], v01 = acc[mt][nt][1];
            float v10 = acc[mt][nt][2], v11 = acc[mt][nt][3];
            int kp = nt * 4 + (lane & 3);
            unsigned h0 = pack_bf16x2(v00, v01);
            unsigned l0p = pack_bf16x2(v00 - bf_lo(h0), v01 - bf_hi(h0));
            unsigned h1 = pack_bf16x2(v10, v11);
            unsigned l1p = pack_bf16x2(v10 - bf_lo(h1), v11 - bf_hi(h1));
            float p00 = __shfl_xor_sync(0xFFFFFFFFu, v00, 4);
            float p01 = __shfl_xor_sync(0xFFFFFFFFu, v01, 4);
            float p10 = __shfl_xor_sync(0xFFFFFFFFu, v10, 4);
            float p11 = __shfl_xor_sync(0xFFFFFFFFu, v11, 4);
            if (mode == 1) {
                int b = r >> 12, l = r & 4095;
                int baseRM = ((b * NHq + n_h) * 4096 + l) * 16 + kp;
                g_chP2[baseRM]       = make_uint2(h0, l0p);
                g_chP2[baseRM + 128] = make_uint2(h1, l1p);
                if (evq) {
                    int ci = (lane & 3) * 2 + nt * 8;
                    int lp = l >> 1;
                    unsigned th0 = pack_bf16x2(v00, p00);
                    unsigned tl0 = pack_bf16x2(v00 - bf_lo(th0), p00 - bf_hi(th0));
                    unsigned th1 = pack_bf16x2(v01, p01);
                    unsigned tl1 = pack_bf16x2(v01 - bf_lo(th1), p01 - bf_hi(th1));
                    unsigned th2 = pack_bf16x2(v10, p10);
                    unsigned tl2 = pack_bf16x2(v10 - bf_lo(th2), p10 - bf_hi(th2));
                    unsigned th3 = pack_bf16x2(v11, p11);
                    unsigned tl3 = pack_bf16x2(v11 - bf_lo(th3), p11 - bf_hi(th3));
                    int baseT = ((b * NHq + n_h) * 32 + ci) * 2048 + lp;
                    g_chT2[baseT]            = make_uint2(th0, tl0);
                    g_chT2[baseT + 2048]     = make_uint2(th1, tl1);
                    g_chT2[baseT + 4]        = make_uint2(th2, tl2);
                    g_chT2[baseT + 2048 + 4] = make_uint2(th3, tl3);
                }
            } else {
                int b = r >> 6, t = r & 63;
                int baseRM = ((b * NHq + n_h) * 64 + t) * 16 + kp;
                g_tyP2[baseRM]       = make_uint2(h0, l0p);
                g_tyP2[baseRM + 128] = make_uint2(h1, l1p);
                if (evq) {
                    int ci = (lane & 3) * 2 + nt * 8;
                    int lp = t >> 1;
                    unsigned th0 = pack_bf16x2(v00, p00);
                    unsigned tl0 = pack_bf16x2(v00 - bf_lo(th0), p00 - bf_hi(th0));
                    unsigned th1 = pack_bf16x2(v01, p01);
                    unsigned tl1 = pack_bf16x2(v01 - bf_lo(th1), p01 - bf_hi(th1));
                    unsigned th2 = pack_bf16x2(v10, p10);
                    unsigned tl2 = pack_bf16x2(v10 - bf_lo(th2), p10 - bf_hi(th2));
                    unsigned th3 = pack_bf16x2(v11, p11);
                    unsigned tl3 = pack_bf16x2(v11 - bf_lo(th3), p11 - bf_hi(th3));
                    int baseT = ((b * NHq + n_h) * 32 + ci) * 32 + lp;
                    g_tyT2[baseT]          = make_uint2(th0, tl0);
                    g_tyT2[baseT + 32]     = make_uint2(th1, tl1);
                    g_tyT2[baseT + 4]      = make_uint2(th2, tl2);
                    g_tyT2[baseT + 32 + 4] = make_uint2(th3, tl3);
                }
            }
        }
    }
}

// ---------------- attention core v6: pre-packed operands, fat tiles -------------
#define OFF_XT    0        // crossT hi 640 / lo +640  (32 x 20)
#define OFF_CHa   1280     // CH hi 1600 / lo +1600    (80 x 20)
#define OFF_TY    4480     // types hi 1280 / lo +1280 (64 x 20)
#define OFF_CQ    7040     // CQ hi 1280 / lo +1280    (64 x 20)
#define OFF_WW    0        // alias: Wwin hi 2816 / lo +2816 (64 x 44)
#define OFF_WT    5632     // alias: Wt hi 2304 / lo +2304   (64 x 36)
#define OFF_TT    10240    // typesT hi 1152 / lo +1152 (32 x 36)
#define OFF_CT    12544    // CHT hi 1408 / lo +1408    (32 x 44)
#define OFF_LT    15360    // logitsT float [64][68]
#define OFF_G     19712    // band G float [64][21]
#define OFF_UQ    21056
#define OFF_DS    21136
#define OFF_MK    21216
#define OFF_DT    21296
#define SMEM_UINTS 21360
#define ATTN_SMEM_BYTES (SMEM_UINTS * 4)

__global__ __launch_bounds__(512, 2) void attn_mma6_kernel(
    const void* __restrict__ maskp, const float* __restrict__ context)
{
    extern __shared__ unsigned SU[];
    float* SF = (float*)SU;
    const int tid = threadIdx.x, wid = tid >> 5, lane = tid & 31;
    const int n = blockIdx.y, b = blockIdx.z;
    const int l0 = blockIdx.x * 64;
    const int mmode = mask_mode(maskp);
    const int b8n = b * NHq + n;
    const int bnL = b8n * Lq;
    const long maskbase = (long)b * Lq;

    // ---------------- stage (pure uint2 copies) ----------------
    for (int i = tid; i < 1280; i += 512) {        // CH rows 80 x 16
        int row = i >> 4, kp = i & 15;
        int l = l0 + row; if (l > Lq - 1) l = Lq - 1;
        uint2 w = g_chP2[(b8n * 4096 + l) * 16 + kp];
        SU[OFF_CHa + row * 20 + kp] = w.x;
        SU[OFF_CHa + 1600 + row * 20 + kp] = w.y;
    }
    for (int i = tid; i < 1280; i += 512) {        // CHT 32 x 40
        int d = i / 40, lp = i - d * 40;
        int lpa = (l0 >> 1) + lp; if (lpa > 2047) lpa = 2047;
        uint2 w = g_chT2[(b8n * 32 + d) * 2048 + lpa];
        SU[OFF_CT + d * 44 + lp] = w.x;
        SU[OFF_CT + 1408 + d * 44 + lp] = w.y;
    }
    for (int i = tid; i < 1024; i += 512) {        // types 64 x 16
        uint2 w = g_tyP2[b8n * 1024 + i];
        int t = i >> 4, kp = i & 15;
        SU[OFF_TY + t * 20 + kp] = w.x;
        SU[OFF_TY + 1280 + t * 20 + kp] = w.y;
    }
    for (int i = tid; i < 1024; i += 512) {        // typesT 32 x 32
        uint2 w = g_tyT2[b8n * 1024 + i];
        int d = i >> 5, lp = i & 31;
        SU[OFF_TT + d * 36 + lp] = w.x;
        SU[OFF_TT + 1152 + d * 36 + lp] = w.y;
    }
    if (tid < 512) {                                // crossT 32 x 16
        int i = tid;
        if (i < 512) {
            uint2 w = g_xP2[n * 512 + i];
            int h = i >> 4, kp = i & 15;
            SU[OFF_XT + h * 20 + kp] = w.x;
            SU[OFF_XT + 640 + h * 20 + kp] = w.y;
        }
    }
    for (int i = tid; i < 80; i += 512) {
        int ru = l0 + i; if (ru > Lq - 1) ru = Lq - 1;
        SF[OFF_UQ + i] = g_uq[bnL + ru];
        SF[OFF_MK + i] = mask_at(maskp, mmode, maskbase + ru) ? 1.f : 0.f;
        int rd = l0 + i - 16; if (rd < 0) rd = 0;
        SF[OFF_DS + i] = g_ds[bnL + rd];
    }
    for (int i = tid; i < 64; i += 512) SF[OFF_DT + i] = g_dt[b8n * Tq + i];
    __syncthreads();

    // ---------------- phase A: CQ = CH @ crossT (8 fat warps) ----------------
    if (wid < 8) {
        const int mt = wid >> 1, nhp = wid & 1;
        float acc[2][4] = {{0,0,0,0},{0,0,0,0}};
#pragma unroll
        for (int k16 = 0; k16 < 2; k16++) {
            unsigned ahi[4], alo[4];
            gatherA16(SU + OFF_CHa, 20, mt * 16, k16 * 8, lane, ahi);
            gatherA16(SU + OFF_CHa + 1600, 20, mt * 16, k16 * 8, lane, alo);
#pragma unroll
            for (int j = 0; j < 2; j++) {
                unsigned bhi[2], blo[2];
                gatherB16(SU + OFF_XT, 20, (nhp * 2 + j) * 8, k16 * 8, lane, bhi);
                gatherB16(SU + OFF_XT + 640, 20, (nhp * 2 + j) * 8, k16 * 8, lane, blo);
                mma3(acc[j], ahi, alo, bhi, blo);
            }
        }
        const int rlo = mt * 16 + (lane >> 2);
#pragma unroll
        for (int j = 0; j < 2; j++) {
            const int cp = (nhp * 2 + j) * 4 + (lane & 3);
            unsigned h0 = pack_bf16x2(acc[j][0], acc[j][1]);
            unsigned l0p = pack_bf16x2(acc[j][0] - bf_lo(h0), acc[j][1] - bf_hi(h0));
            unsigned h1 = pack_bf16x2(acc[j][2], acc[j][3]);
            unsigned l1p = pack_bf16x2(acc[j][2] - bf_lo(h1), acc[j][3] - bf_hi(h1));
            SU[OFF_CQ + rlo * 20 + cp]              = h0;
            SU[OFF_CQ + 1280 + rlo * 20 + cp]       = l0p;
            SU[OFF_CQ + (rlo + 8) * 20 + cp]        = h1;
            SU[OFF_CQ + 1280 + (rlo + 8) * 20 + cp] = l1p;
        }
    }
    __syncthreads();

    // ---------------- phase B: logits (warps 0-7) / band G (warps 8-11) -------
    if (wid < 8) {
        const int mt = wid >> 1, half = wid & 1;
        float acc2[4][4];
#pragma unroll
        for (int i = 0; i < 4; i++)
#pragma unroll
            for (int r = 0; r < 4; r++) acc2[i][r] = 0.f;
#pragma unroll
        for (int k16 = 0; k16 < 2; k16++) {
            unsigned ahi[4], alo[4];
            gatherA16(SU + OFF_CQ, 20, mt * 16, k16 * 8, lane, ahi);
            gatherA16(SU + OFF_CQ + 1280, 20, mt * 16, k16 * 8, lane, alo);
#pragma unroll
            for (int j = 0; j < 4; j++) {
                int ntg = half * 4 + j;
                unsigned bhi[2], blo[2];
                gatherB16(SU + OFF_TY, 20, ntg * 8, k16 * 8, lane, bhi);
                gatherB16(SU + OFF_TY + 1280, 20, ntg * 8, k16 * 8, lane, blo);
                mma3(acc2[j], ahi, alo, bhi, blo);
            }
        }
        const int rlo = mt * 16 + (lane >> 2);
#pragma unroll
        for (int j = 0; j < 4; j++) {
            int c0 = (half * 4 + j) * 8 + 2 * (lane & 3);
            *(float2*)&SF[OFF_LT + rlo * 68 + c0]       = make_float2(acc2[j][0], acc2[j][1]);
            *(float2*)&SF[OFF_LT + (rlo + 8) * 68 + c0] = make_float2(acc2[j][2], acc2[j][3]);
        }
    } else if (wid < 12) {
        const int rb = wid - 8;
        float accg[4][4];
#pragma unroll
        for (int i = 0; i < 4; i++)
#pragma unroll
            for (int r = 0; r < 4; r++) accg[i][r] = 0.f;
#pragma unroll
        for (int k16 = 0; k16 < 2; k16++) {
            unsigned ahi[4], alo[4];
            gatherA16(SU + OFF_CQ, 20, rb * 16, k16 * 8, lane, ahi);
            gatherA16(SU + OFF_CQ + 1280, 20, rb * 16, k16 * 8, lane, alo);
#pragma unroll
            for (int nt = 0; nt < 4; nt++) {
                unsigned bhi[2], blo[2];
                gatherB16(SU + OFF_CHa, 20, rb * 16 + nt * 8, k16 * 8, lane, bhi);
                gatherB16(SU + OFF_CHa + 1600, 20, rb * 16 + nt * 8, k16 * 8, lane, blo);
                mma3(accg[nt], ahi, alo, bhi, blo);
            }
        }
        const int rlo = rb * 16 + (lane >> 2), rhi = rlo + 8;
#pragma unroll
        for (int nt = 0; nt < 4; nt++) {
            int m0 = rb * 16 + nt * 8 + 2 * (lane & 3);
            int k;
            k = m0 - rlo;     if (k >= 0 && k <= 16) SF[OFF_G + rlo * 21 + k] = accg[nt][0];
            k = m0 + 1 - rlo; if (k >= 0 && k <= 16) SF[OFF_G + rlo * 21 + k] = accg[nt][1];
            k = m0 - rhi;     if (k >= 0 && k <= 16) SF[OFF_G + rhi * 21 + k] = accg[nt][2];
            k = m0 + 1 - rhi; if (k >= 0 && k <= 16) SF[OFF_G + rhi * 21 + k] = accg[nt][3];
        }
    }
    __syncthreads();

    // ---------------- zero Wwin pool ----------------
    {
        uint4 z = make_uint4(0, 0, 0, 0);
        for (int i = tid; i < 1408; i += 512) ((uint4*)SU)[i] = z;
    }
    __syncthreads();

    // ---------------- softmax (4 rows per warp) ----------------
    {
        const float dt0 = SF[OFF_DT + lane];
        const float dt1 = SF[OFF_DT + lane + 32];
        for (int i = 0; i < 4; i++) {
            const int r = wid * 4 + i;
            const int l = l0 + r;
            const float uq_l = SF[OFF_UQ + r];

            float lt0 = leaky(uq_l + dt0 + SF[OFF_LT + r * 68 + lane]);
            float lt1 = leaky(uq_l + dt1 + SF[OFF_LT + r * 68 + 32 + lane]);

            const int ku = (lane <= 16) ? 0 : lane - 16;
            const int kd = (lane < 16) ? lane - 16 : 0;
            const bool ok = (l + kd >= 0) && (l + ku < Lq);
            const bool mk = ok && (SF[OFF_MK + r + ku] != 0.f);
            float lg = leaky(SF[OFF_UQ + r + ku] + SF[OFF_DS + r + kd + 16] + SF[OFF_G + r * 21 + ku]);
            float lw = mk ? lg : MASK_FILL;

            float lw2 = -INFINITY;
            if (lane == 0) {
                const bool ok2 = (l + 16 < Lq);
                const bool mk2 = ok2 && (SF[OFF_MK + r + 16] != 0.f);
                float lg2 = leaky(SF[OFF_UQ + r + 16] + SF[OFF_DS + r + 16] + SF[OFF_G + r * 21 + 16]);
                lw2 = mk2 ? lg2 : MASK_FILL;
            }

            float mx = fmaxf(fmaxf(lt0, lt1), lw);
            if (lane == 0) mx = fmaxf(mx, lw2);
#pragma unroll
            for (int o = 16; o; o >>= 1) mx = fmaxf(mx, __shfl_xor_sync(0xFFFFFFFFu, mx, o));
            float e0 = __expf(lt0 - mx), e1 = __expf(lt1 - mx), ew = __expf(lw - mx);
            float ew2 = (lane == 0) ? __expf(lw2 - mx) : 0.f;
            float sm = e0 + e1 + ew + ew2;
#pragma unroll
            for (int o = 16; o; o >>= 1) sm += __shfl_xor_sync(0xFFFFFFFFu, sm, o);
            const float inv = 1.0f / sm;

            store_split(SU + OFF_WT, SU + OFF_WT + 2304, r * 72 + lane,      e0 * inv);
            store_split(SU + OFF_WT, SU + OFF_WT + 2304, r * 72 + lane + 32, e1 * inv);

            float wwl = ew * inv;
            float wband = (lane <= 16) ? wwl : 0.f;
#pragma unroll
            for (int o = 16; o; o >>= 1) wband += __shfl_xor_sync(0xFFFFFFFFu, wband, o);
            if (lane == 0) {
                store_split(SU + OFF_WW, SU + OFF_WW + 2816, r * 88 + r,      wband);
                store_split(SU + OFF_WW, SU + OFF_WW + 2816, r * 88 + r + 16, ew2 * inv);
            } else if (lane >= 17) {
                store_split(SU + OFF_WW, SU + OFF_WW + 2816, r * 88 + r + (lane - 16), wwl);
            }
        }
    }
    __syncthreads();

    // ---------------- update (8 fat warps; window part band-limited) -----------
    if (wid < 8) {
        const int mt = wid >> 1;
        const int nthp = wid & 1;
        float acc[2][4] = {{0,0,0,0},{0,0,0,0}};
#pragma unroll
        for (int k16 = 0; k16 < 4; k16++) {
            unsigned ahi[4], alo[4];
            gatherA16(SU + OFF_WT, 36, mt * 16, k16 * 8, lane, ahi);
            gatherA16(SU + OFF_WT + 2304, 36, mt * 16, k16 * 8, lane, alo);
#pragma unroll
            for (int j = 0; j < 2; j++) {
                unsigned bhi[2], blo[2];
                gatherB16(SU + OFF_TT, 36, (nthp * 2 + j) * 8, k16 * 8, lane, bhi);
                gatherB16(SU + OFF_TT + 1152, 36, (nthp * 2 + j) * 8, k16 * 8, lane, blo);
                mma3(acc[j], ahi, alo, bhi, blo);
            }
        }
#pragma unroll
        for (int k16 = 0; k16 < 2; k16++) {
            const int KP0 = mt * 8 + k16 * 8;
            unsigned ahi[4], alo[4];
            gatherA16(SU + OFF_WW, 44, mt * 16, KP0, lane, ahi);
            gatherA16(SU + OFF_WW + 2816, 44, mt * 16, KP0, lane, alo);
#pragma unroll
            for (int j = 0; j < 2; j++) {
                unsigned bhi[2], blo[2];
                gatherB16(SU + OFF_CT, 44, (nthp * 2 + j) * 8, KP0, lane, bhi);
                gatherB16(SU + OFF_CT + 1408, 44, (nthp * 2 + j) * 8, KP0, lane, blo);
                mma3(acc[j], ahi, alo, bhi, blo);
            }
        }
        const int llo = l0 + mt * 16 + (lane >> 2);
#pragma unroll
        for (int j = 0; j < 2; j++) {
            const int col = n * 32 + (nthp * 2 + j) * 8 + 2 * (lane & 3);
            size_t g0 = (size_t)(b * Lq + llo) * Hq + col;
            size_t g1 = (size_t)(b * Lq + llo + 8) * Hq + col;
            float2 c0 = *(const float2*)&context[g0];
            float2 c1 = *(const float2*)&context[g1];
            *(float2*)&g_U[g0] = make_float2(acc[j][0] + c0.x, acc[j][1] + c0.y);
            *(float2*)&g_U[g1] = make_float2(acc[j][2] + c1.x, acc[j][3] + c1.y);
        }
    }
}

// ---------------- launch ----------------
extern "C" void kernel_launch(void* const* d_in, const int* in_sizes, int n_in,
                              void* d_out, int out_size)
{
    (void)in_sizes; (void)n_in; (void)out_size;
    const float* context   = (const float*)d_in[0];
    const float* types     = (const float*)d_in[1];
    const void*  cmask     = d_in[2];
    const float* W_types   = (const float*)d_in[3];
    const float* b_types   = (const float*)d_in[4];
    const float* W_context = (const float*)d_in[5];
    const float* b_context = (const float*)d_in[6];
    const float* upon      = (const float*)d_in[7];
    const float* down      = (const float*)d_in[8];
    const float* cross     = (const float*)d_in[9];
    const float* W_out     = (const float*)d_in[10];
    const float* b_out     = (const float*)d_in[11];
    float* out = (float*)d_out;

    float* p_U;
    cudaGetSymbolAddress((void**)&p_U, g_U);

    cudaFuncSetAttribute(attn_mma6_kernel,
                         cudaFuncAttributeMaxDynamicSharedMemorySize, ATTN_SMEM_BYTES);

    prep_weights<<<dim3(8, 8, 3), 256>>>(W_types, W_context, W_out);
    prep_cross<<<1, 256>>>(cross);
    // types_h packed + fused dt
    gemm_bf16x3<<<dim3(4, 2), 256>>>(types, 0, b_types, nullptr, 2, upon, down);
    // context_h packed + fused uq/ds
    gemm_bf16x3<<<dim3(4, 128), 256>>>(context, 1, b_context, nullptr, 1, upon, down);
    // attention -> g_U = update + context
    attn_mma6_kernel<<<dim3(Lq / 64, NHq, Bq), 512, ATTN_SMEM_BYTES>>>(cmask, context);
    // out = tanh(g_U @ W_out + b_out)
    gemm_bf16x3<<<dim3(4, 128), 256>>>(p_U, 2, b_out, out, 0, upon, down);
}